// round 14
// baseline (speedup 1.0000x reference)
#include <cuda_runtime.h>
#include <cuda_bf16.h>

// SEIR Euler — fused producer/consumer with redundant-prefix SPLIT.
//
// Model (validated over rounds 6-12): achieved write BW tracks total
// concurrent store streams per SM. Fused/1024-CTA tops out at 5.5 TB/s;
// the 8192-CTA dedicated store kernel hit 6.05. Fix: SPLIT the chunk range
// per region-group across SPLIT CTAs. Each split CTA's producer warp silently
// re-chains the prefix (cheap fma, pipe at 14%), then publishes only its own
// chunk window. 2x CTAs -> ~2x store warps in flight. All sync intra-CTA.

#define CHUNK      32
#define MAX_CHUNKS 32          // fused path supports t <= 1024
#define BPC        32          // regions per CTA (= producer warp lanes)
#define BLOCK      256
#define GRAB       2
#define SPLIT      2

__device__ __forceinline__ float4 seir_step(float4 v, float bh, float gh, float sh)
{
    const float S = v.x, E = v.y, I = v.z, R = v.w;
    const float p = bh * S;
    float4 r;
    r.x = __fmaf_rn(-p, I, S);
    r.y = __fmaf_rn( p, I, __fmaf_rn(-sh, E, E));
    r.z = __fmaf_rn( sh, E, __fmaf_rn(-gh, I, I));
    r.w = __fmaf_rn( gh, I, R);
    return r;
}

__global__ void __launch_bounds__(BLOCK) seir_fused_kernel(
    const float* __restrict__ initial,
    const float* __restrict__ beta,
    const float* __restrict__ gamma,
    const float* __restrict__ sigma,
    float4* __restrict__ out,
    int B, int t)
{
    __shared__ float4   ckpt[MAX_CHUNKS][BPC];
    __shared__ unsigned flags[MAX_CHUNKS];
    __shared__ unsigned work_ctr;

    const int g    = blockIdx.x;
    const int grp  = g / SPLIT;               // region group
    const int s    = g - grp * SPLIT;         // split index (chunk window)
    const int tid  = threadIdx.x;
    const int wid  = tid >> 5;
    const int lane = tid & 31;

    const int nchunks = t / CHUNK;            // exact in fused path
    const int cpp     = nchunks / SPLIT;      // chunks per CTA
    const int c_off   = s * cpp;              // this CTA's first global chunk
    const int base_b  = grp * BPC;

    const float step = 0.5f;
    const float bh = beta[0]  * step;
    const float gh = gamma[0] * step;
    const float sh = sigma[0] * step;

    for (int i = tid; i < MAX_CHUNKS; i += BLOCK) flags[i] = 0u;
    if (tid == 0) work_ctr = 0u;
    __syncthreads();

    volatile unsigned* vflags = flags;

    if (wid == 0) {
        // ---- Producer: silent prefix, then publish this CTA's window ----
        const int b = base_b + lane;
        float4 v = make_float4(initial[0 * B + b], initial[1 * B + b],
                               initial[2 * B + b], initial[3 * B + b]);
        const int prefix = c_off * CHUNK;
        #pragma unroll 8
        for (int n = 0; n < prefix; ++n)
            v = seir_step(v, bh, gh, sh);

        for (int c = 0; c < cpp; ++c) {
            ckpt[c][lane] = v;
            __stcs(&out[(size_t)(c_off + c) * CHUNK * B + b], v);
            __syncwarp();
            if (lane == 0) { __threadfence_block(); vflags[c] = 1u; }
            if (c + 1 < cpp) {
                #pragma unroll 8
                for (int j = 0; j < CHUNK; ++j)
                    v = seir_step(v, bh, gh, sh);
            }
        }
        // fall through: producer joins the consumer pool
    }

    // ---- Consumers (all warps): pull GRAB chunks per queue grab ----
    for (;;) {
        unsigned base;
        if (lane == 0) base = atomicAdd(&work_ctr, (unsigned)GRAB);
        base = __shfl_sync(0xFFFFFFFFu, base, 0);
        if (base >= (unsigned)cpp) break;

        const int c0 = (int)base;
        const int cmax = min(c0 + GRAB - 1, cpp - 1);

        // Flags are set in increasing order -> waiting on cmax covers all.
        while (vflags[cmax] == 0u) { }
        __threadfence_block();

        if (c0 + GRAB <= cpp) {
            // ILP-2: two independent chain+store streams.
            float4 v0 = ckpt[c0 + 0][lane];
            float4 v1 = ckpt[c0 + 1][lane];
            size_t i0 = (size_t)(c_off + c0 + 0) * CHUNK * B + base_b + lane;
            size_t i1 = (size_t)(c_off + c0 + 1) * CHUNK * B + base_b + lane;
            #pragma unroll
            for (int j = 1; j < CHUNK; ++j) {
                v0 = seir_step(v0, bh, gh, sh);
                v1 = seir_step(v1, bh, gh, sh);
                i0 += B; i1 += B;
                __stcs(&out[i0], v0);
                __stcs(&out[i1], v1);
            }
        } else {
            for (int c = c0; c <= cmax; ++c) {
                float4 v = ckpt[c][lane];
                size_t idx = (size_t)(c_off + c) * CHUNK * B + base_b + lane;
                #pragma unroll
                for (int j = 1; j < CHUNK; ++j) {
                    v = seir_step(v, bh, gh, sh);
                    idx += B;
                    __stcs(&out[idx], v);
                }
            }
        }
    }
}

// ---- Fallback two-kernel path (known-good) for generic shapes ----
__global__ void __launch_bounds__(128) seir_ckpt_kernel(
    const float* __restrict__ initial, const float* __restrict__ beta,
    const float* __restrict__ gamma,   const float* __restrict__ sigma,
    float4* __restrict__ out, int B, int t)
{
    const int b = blockIdx.x * blockDim.x + threadIdx.x;
    if (b >= B) return;
    const float step = 0.5f;
    const float bh = beta[0]*step, gh = gamma[0]*step, sh = sigma[0]*step;
    float4 v = make_float4(initial[0*B+b], initial[1*B+b],
                           initial[2*B+b], initial[3*B+b]);
    out[b] = v;
    const int nchunks = (t + CHUNK - 1) / CHUNK;
    for (int c = 1; c < nchunks; ++c) {
        const int base = (c - 1) * CHUNK;
        const int steps = min(CHUNK, t - base);
        for (int j = 0; j < steps; ++j) v = seir_step(v, bh, gh, sh);
        if (c * CHUNK < t) out[(size_t)c * CHUNK * B + b] = v;
    }
}

__global__ void __launch_bounds__(256) seir_store_kernel(
    const float* __restrict__ beta, const float* __restrict__ gamma,
    const float* __restrict__ sigma, float4* __restrict__ out,
    int B, int t)
{
    const int tid = blockIdx.x * blockDim.x + threadIdx.x;
    const int c  = tid / B;
    const int bb = tid - c * B;
    const int n0 = c * CHUNK;
    if (n0 >= t || bb >= B) return;
    const float step = 0.5f;
    const float bh = beta[0]*step, gh = gamma[0]*step, sh = sigma[0]*step;
    size_t idx = (size_t)n0 * B + bb;
    float4 v = out[idx];
    const int nlast = min(n0 + CHUNK, t);
    for (int n = n0 + 1; n < nlast; ++n) {
        v = seir_step(v, bh, gh, sh);
        idx += B;
        __stcs(&out[idx], v);
    }
}

extern "C" void kernel_launch(void* const* d_in, const int* in_sizes, int n_in,
                              void* d_out, int out_size)
{
    const float* initial = (const float*)d_in[0];   // 4*B elements
    const float* beta    = (const float*)d_in[1];
    const float* gamma   = (const float*)d_in[2];
    const float* sigma   = (const float*)d_in[3];

    const int B = in_sizes[0] / 4;
    const int t = (B > 0) ? (out_size / (4 * B)) : 0;
    if (B <= 0 || t <= 0) return;

    const int nchunks = (t + CHUNK - 1) / CHUNK;

    if ((B % BPC) == 0 && (t % CHUNK) == 0 &&
        nchunks <= MAX_CHUNKS && (nchunks % SPLIT) == 0) {
        seir_fused_kernel<<<(B / BPC) * SPLIT, BLOCK>>>(
            initial, beta, gamma, sigma, (float4*)d_out, B, t);
    } else {
        const long long total = (long long)nchunks * B;
        seir_ckpt_kernel<<<(B + 127) / 128, 128>>>(initial, beta, gamma, sigma,
                                                   (float4*)d_out, B, t);
        seir_store_kernel<<<(int)((total + 255) / 256), 256>>>(
            beta, gamma, sigma, (float4*)d_out, B, t);
    }
}